// round 12
// baseline (speedup 1.0000x reference)
#include <cuda_runtime.h>
#include <cuda_fp16.h>
#include <cuda_fp8.h>
#include <math.h>

#define DD  128
#define HW  16384            // 128*128
#define VOL 2097152          // 128^3
#define TY  16               // y-tile for blurYX
#define NSCI (1.0f / 32.0f)  // fp8 noise decode scale

struct __align__(16) h4p { __half2 a, b, c, d; };
struct __align__(8)  h4  { __half2 a, b; };

// ---- scratch (static device globals, allocation-free) ----
__device__ uint4        g_eA[VOL];         // 32 MB: paired (fp8 noise, imgA, labA)
__device__ uint4        g_eB[VOL];         // 32 MB: paired (fp8 noise, imgB, labB)
__device__ uint4        g_tmpFp[VOL];      // 32 MB: paired warp(Ieps, AB) fp16
__device__ uint4        g_tmpBp[VOL];      // 32 MB: paired warp(Ieps, BA) fp16
__device__ unsigned int g_n4[VOL];         //  8 MB: fp8 noise triple (linear Ieps)
__device__ __half       g_WAh[VOL];        //  4 MB: warp(imgA, AB)
__device__ __half       g_WBh[VOL];        //  4 MB: warp(imgB, BA)
__device__ __half2      g_I2[VOL];         //  8 MB: (imgA, imgB)
__device__ __half       g_blur[10 * VOL];  // 40 MB: z-blurred channels
__device__ double       g_acc[16];

__constant__ float c_gk[5] = {
    0.05448868454964294f, 0.24420134200323332f, 0.40261995089424437f,
    0.24420134200323332f, 0.05448868454964294f };

__device__ __forceinline__ float idgv(int v) { return -1.0f + (float)v * (2.0f / 127.0f); }

__device__ __forceinline__ void axis_prep(float c, float& w0, float& w1, int& i0, int& i1) {
    float f  = floorf(c);
    float fr = c - f;
    int j0 = (int)f;
    w0 = (j0 >= 0 && j0 < DD)       ? (1.0f - fr) : 0.0f;
    w1 = (j0 >= -1 && j0 <= DD - 2) ? fr          : 0.0f;
    i0 = min(max(j0, 0), DD - 1);
    i1 = min(max(j0 + 1, 0), DD - 1);
}

__device__ __forceinline__ void axis_prep_pair(float c, float& pw0, float& pw1, int& base) {
    float f  = floorf(c);
    float fr = c - f;
    int j0 = (int)f;
    float w0 = (j0 >= 0 && j0 < DD)       ? (1.0f - fr) : 0.0f;
    float w1 = (j0 >= -1 && j0 <= DD - 2) ? fr          : 0.0f;
    if (j0 < 0) { pw0 = w1; pw1 = 0.0f; }
    else        { pw0 = w0; pw1 = w1;  }
    base = min(max(j0, 0), DD - 1);
}

struct AxesP {
    float wz[2], wy[2];
    int   iz[2], iy[2];
    float pwx0, pwx1;
    int   ixb;
};

__device__ __forceinline__ AxesP make_axesP(const float* __restrict__ phi, int i) {
    AxesP a;
    float z = (phi[i]           + 1.0f) * 63.5f;
    float y = (phi[VOL + i]     + 1.0f) * 63.5f;
    float x = (phi[2 * VOL + i] + 1.0f) * 63.5f;
    axis_prep(z, a.wz[0], a.wz[1], a.iz[0], a.iz[1]);
    axis_prep(y, a.wy[0], a.wy[1], a.iy[0], a.iy[1]);
    axis_prep_pair(x, a.pwx0, a.pwx1, a.ixb);
    return a;
}

__device__ __forceinline__ void corners(const AxesP& a, int idx[4], float w0[4], float w1[4]) {
#pragma unroll
    for (int dz = 0; dz < 2; dz++)
#pragma unroll
        for (int dy = 0; dy < 2; dy++) {
            int j = dz * 2 + dy;
            idx[j] = a.iz[dz] * HW + a.iy[dy] * DD + a.ixb;
            float wzy = a.wz[dz] * a.wy[dy];
            w0[j] = wzy * a.pwx0;
            w1[j] = wzy * a.pwx1;
        }
}

__device__ __forceinline__ void dec_n3(unsigned int u0, float& n0, float& n1, float& n2) {
    __half2_raw h01 = __nv_cvt_fp8x2_to_halfraw2((__nv_fp8x2_storage_t)(u0 & 0xFFFFu), __NV_E4M3);
    __half2_raw h2r = __nv_cvt_fp8x2_to_halfraw2((__nv_fp8x2_storage_t)((u0 >> 16) & 0xFFFFu), __NV_E4M3);
    float2 f01 = __half22float2(*(__half2*)&h01);
    float2 f2  = __half22float2(*(__half2*)&h2r);
    n0 = f01.x; n1 = f01.y; n2 = f2.x;
}

struct F5 { float n0, n1, n2, img, lab; };

__device__ __forceinline__ void acc_e8(const uint4& v, float w0, float w1, F5& r) {
    float a0, a1, a2, b0, b1, b2;
    dec_n3(v.x, a0, a1, a2);
    dec_n3(v.z, b0, b1, b2);
    float2 ilA = __half22float2(*(__half2*)&v.y);
    float2 ilB = __half22float2(*(__half2*)&v.w);
    r.n0 += w0 * a0 + w1 * b0;
    r.n1 += w0 * a1 + w1 * b1;
    r.n2 += w0 * a2 + w1 * b2;
    r.img += w0 * ilA.x + w1 * ilB.x;
    r.lab += w0 * ilA.y + w1 * ilB.y;
}

__device__ __forceinline__ void acc_h4p(const uint4& v, float w0, float w1, float3& r) {
    h4p h = *(const h4p*)&v;
    float2 p0 = __half22float2(h.a);
    float  q0 = __half2float(h.b.x);
    float2 p1 = __half22float2(h.c);
    float  q1 = __half2float(h.d.x);
    r.x += w0 * p0.x + w1 * p1.x;
    r.y += w0 * p0.y + w1 * p1.y;
    r.z += w0 * q0   + w1 * q1;
}

__device__ __forceinline__ float3 warp_idgP(const AxesP& a) {
    float Sz0 = a.wz[0] + a.wz[1];
    float Sy0 = a.wy[0] + a.wy[1];
    float Sx0 = a.pwx0 + a.pwx1;
    float Sz1 = a.wz[0] * idgv(a.iz[0]) + a.wz[1] * idgv(a.iz[1]);
    float Sy1 = a.wy[0] * idgv(a.iy[0]) + a.wy[1] * idgv(a.iy[1]);
    float Sx1 = a.pwx0 * idgv(a.ixb) + a.pwx1 * idgv(min(a.ixb + 1, DD - 1));
    return make_float3(Sz1 * Sy0 * Sx0, Sz0 * Sy1 * Sx0, Sz0 * Sy0 * Sx1);
}

__device__ __forceinline__ void block_add(double v, double* dst) {
    __shared__ double sm[8];
    int lane = threadIdx.x & 31;
    int wid  = threadIdx.x >> 5;
#pragma unroll
    for (int o = 16; o > 0; o >>= 1) v += __shfl_down_sync(0xffffffffu, v, o);
    __syncthreads();
    if (lane == 0) sm[wid] = v;
    __syncthreads();
    if (wid == 0) {
        double t = (lane < 8) ? sm[lane] : 0.0;
#pragma unroll
        for (int o = 4; o > 0; o >>= 1) t += __shfl_down_sync(0xffffffffu, t, o);
        if (lane == 0) atomicAdd(dst, t);
    }
}

__global__ void k_init() {
    if (threadIdx.x < 16) g_acc[threadIdx.x] = 0.0;
}

// pack: paired e8 arrays (smem-staged), n4, I2, dice denominators. 4 vox/thread.
__global__ void k_pack(const float* __restrict__ noise,
                       const float* __restrict__ imgA, const float* __restrict__ labA,
                       const float* __restrict__ imgB, const float* __restrict__ labB) {
    __shared__ uint2 sA[1024], sB[1024];
    int tid = threadIdx.x;
    int base = blockIdx.x * 1024;
    int l0 = tid * 4;
    int i4 = base + l0;

    float4 n0 = *(const float4*)&noise[i4];
    float4 n1 = *(const float4*)&noise[VOL + i4];
    float4 n2 = *(const float4*)&noise[2 * VOL + i4];
    float4 ia = *(const float4*)&imgA[i4];
    float4 la = *(const float4*)&labA[i4];
    float4 ib = *(const float4*)&imgB[i4];
    float4 lb = *(const float4*)&labB[i4];

    const float* pn0 = &n0.x; const float* pn1 = &n1.x; const float* pn2 = &n2.x;
    const float* pia = &ia.x; const float* pla = &la.x;
    const float* pib = &ib.x; const float* plb = &lb.x;

#pragma unroll
    for (int k = 0; k < 4; k++) {
        unsigned int b0 = (unsigned int)__nv_cvt_float_to_fp8(pn0[k] * 0.25f, __NV_SATFINITE, __NV_E4M3);
        unsigned int b1 = (unsigned int)__nv_cvt_float_to_fp8(pn1[k] * 0.25f, __NV_SATFINITE, __NV_E4M3);
        unsigned int b2 = (unsigned int)__nv_cvt_float_to_fp8(pn2[k] * 0.25f, __NV_SATFINITE, __NV_E4M3);
        unsigned int u0 = b0 | (b1 << 8) | (b2 << 16);
        __half2 hA = __floats2half2_rn(pia[k], pla[k]);
        __half2 hB = __floats2half2_rn(pib[k], plb[k]);
        sA[l0 + k] = make_uint2(u0, *(unsigned int*)&hA);
        sB[l0 + k] = make_uint2(u0, *(unsigned int*)&hB);
        g_n4[i4 + k] = u0;
        g_I2[i4 + k] = __floats2half2_rn(pia[k], pib[k]);
    }
    __syncthreads();

#pragma unroll
    for (int k = 0; k < 4; k++) {
        int l = l0 + k;
        int gi = base + l;
        int nb = ((gi & 127) < 127) ? l + 1 : l;
        uint2 a0 = sA[l], a1 = sA[nb];
        uint2 c0 = sB[l], c1 = sB[nb];
        g_eA[gi] = make_uint4(a0.x, a0.y, a1.x, a1.y);
        g_eB[gi] = make_uint4(c0.x, c0.y, c1.x, c1.y);
    }

    double slb = (double)lb.x + (double)lb.y + (double)lb.z + (double)lb.w;
    double sla = (double)la.x + (double)la.y + (double)la.z + (double)la.w;
    block_add(slb, &g_acc[3]);
    block_add(sla, &g_acc[6]);
}

// stage 1: AB direction — tmpF, WA, dice-A sums (4 scattered loads)
__global__ void __launch_bounds__(256) k_warpAB(
        const float* __restrict__ phiAB, const float* __restrict__ labB) {
    __shared__ h4 buf[256];
    int tid = threadIdx.x;
    int i = blockIdx.x * 256 + tid;

    AxesP a = make_axesP(phiAB, i);
    int idx[4]; float w0[4], w1[4];
    corners(a, idx, w0, w1);

    uint4 v[4];
#pragma unroll
    for (int j = 0; j < 4; j++) v[j] = __ldg(&g_eA[idx[j]]);

    F5 fA; fA.n0 = fA.n1 = fA.n2 = fA.img = fA.lab = 0.f;
#pragma unroll
    for (int j = 0; j < 4; j++) acc_e8(v[j], w0[j], w1[j], fA);

    float3 gA = warp_idgP(a);

    buf[tid].a = __floats2half2_rn(gA.x + fA.n0 * NSCI, gA.y + fA.n1 * NSCI);
    buf[tid].b = __floats2half2_rn(gA.z + fA.n2 * NSCI, 0.0f);
    __syncthreads();
    int dn = ((tid & 127) < 127) ? 1 : 0;
    { h4 s0 = buf[tid], s1 = buf[tid + dn];
      g_tmpFp[i] = make_uint4(*(unsigned int*)&s0.a, *(unsigned int*)&s0.b,
                              *(unsigned int*)&s1.a, *(unsigned int*)&s1.b); }

    g_WAh[i] = __float2half_rn(fA.img);

    block_add((double)(fA.lab * labB[i]), &g_acc[1]);
    block_add((double)fA.lab,             &g_acc[2]);
}

// stage 2: BA direction + forward MSE. Axes computed ONCE; eB and tmpF gathered
// at the SAME corner indices (8 batched loads, pairs share cache lines).
__global__ void __launch_bounds__(256) k_warpBA_mseF(
        const float* __restrict__ phiBA, const float* __restrict__ labA) {
    __shared__ h4 buf[256];
    int tid = threadIdx.x;
    int i = blockIdx.x * 256 + tid;

    AxesP a = make_axesP(phiBA, i);
    int idx[4]; float w0[4], w1[4];
    corners(a, idx, w0, w1);

    uint4 vB[4], vF[4];
#pragma unroll
    for (int j = 0; j < 4; j++) vB[j] = __ldg(&g_eB[idx[j]]);
#pragma unroll
    for (int j = 0; j < 4; j++) vF[j] = __ldg(&g_tmpFp[idx[j]]);

    F5 fB; fB.n0 = fB.n1 = fB.n2 = fB.img = fB.lab = 0.f;
#pragma unroll
    for (int j = 0; j < 4; j++) acc_e8(vB[j], w0[j], w1[j], fB);
    float3 f = make_float3(0.f, 0.f, 0.f);
#pragma unroll
    for (int j = 0; j < 4; j++) acc_h4p(vF[j], w0[j], w1[j], f);

    float3 gB = warp_idgP(a);

    // tmpB write (x-paired via smem)
    buf[tid].a = __floats2half2_rn(gB.x + fB.n0 * NSCI, gB.y + fB.n1 * NSCI);
    buf[tid].b = __floats2half2_rn(gB.z + fB.n2 * NSCI, 0.0f);
    __syncthreads();
    int dn = ((tid & 127) < 127) ? 1 : 0;
    { h4 s0 = buf[tid], s1 = buf[tid + dn];
      g_tmpBp[i] = make_uint4(*(unsigned int*)&s0.a, *(unsigned int*)&s0.b,
                              *(unsigned int*)&s1.a, *(unsigned int*)&s1.b); }

    g_WBh[i] = __float2half_rn(fB.img);

    // forward MSE: Ieps(i) vs f = warp(tmpF, BA)(i)
    float n0, n1, n2;
    dec_n3(g_n4[i], n0, n1, n2);
    int zz = i >> 14, yy = (i >> 7) & 127, xx = i & 127;
    float e0 = idgv(zz) + n0 * NSCI;
    float e1 = idgv(yy) + n1 * NSCI;
    float e2 = idgv(xx) + n2 * NSCI;
    float d0 = e0 - f.x, d1 = e1 - f.y, d2 = e2 - f.z;

    block_add((double)(d0*d0) + (double)(d1*d1) + (double)(d2*d2), &g_acc[0]);
    block_add((double)(fB.lab * labA[i]), &g_acc[4]);
    block_add((double)fB.lab,             &g_acc[5]);
}

// stage 3: backward MSE (4 scattered loads) — overlaps blur chain on s1
__global__ void __launch_bounds__(256) k_mseB(const float* __restrict__ phiAB) {
    int i = blockIdx.x * 256 + threadIdx.x;
    AxesP a = make_axesP(phiAB, i);
    int idx[4]; float w0[4], w1[4];
    corners(a, idx, w0, w1);

    uint4 v[4];
#pragma unroll
    for (int j = 0; j < 4; j++) v[j] = __ldg(&g_tmpBp[idx[j]]);

    float3 b = make_float3(0.f, 0.f, 0.f);
#pragma unroll
    for (int j = 0; j < 4; j++) acc_h4p(v[j], w0[j], w1[j], b);

    float n0, n1, n2;
    dec_n3(g_n4[i], n0, n1, n2);
    int zz = i >> 14, yy = (i >> 7) & 127, xx = i & 127;
    float e0 = idgv(zz) + n0 * NSCI;
    float e1 = idgv(yy) + n1 * NSCI;
    float e2 = idgv(xx) + n2 * NSCI;
    float c0 = e0 - b.x, c1 = e1 - b.y, c2 = e2 - b.z;

    block_add((double)(c0*c0) + (double)(c1*c1) + (double)(c2*c2), &g_acc[0]);
}

// z-blur; streaming stores so co-run with mseB doesn't evict gather arrays
__global__ void k_blurZ10() {
    int i = blockIdx.x * 256 + threadIdx.x;
    int z = i >> 14;
    float a[10];
#pragma unroll
    for (int c = 0; c < 10; c++) a[c] = 0.f;
#pragma unroll
    for (int t = 0; t < 5; t++) {
        int zz = z + t - 2;
        if ((unsigned)zz < (unsigned)DD) {
            int off = i + (t - 2) * HW;
            float k = c_gk[t];
            float wa = __half2float(g_WAh[off]);
            float wb = __half2float(g_WBh[off]);
            float2 ij = __half22float2(g_I2[off]);
            float ia = ij.x, jb = ij.y;
            a[0] += k * wa;      a[1] += k * jb;
            a[2] += k * wa * jb; a[3] += k * wa * wa; a[4] += k * jb * jb;
            a[5] += k * ia;      a[6] += k * wb;
            a[7] += k * ia * wb; a[8] += k * ia * ia; a[9] += k * wb * wb;
        }
    }
#pragma unroll
    for (int c = 0; c < 10; c++) __stcs(&g_blur[c * VOL + i], __float2half_rn(a[c]));
}

__global__ void k_blurYX_red() {
    extern __shared__ char smraw[];
    __half* sin_ = (__half*)smraw;
    float*  srow = (float*)(smraw + 10 * (TY + 4) * 128 * 2);

    int tid = threadIdx.x;
    int z   = blockIdx.x >> 3;
    int y0  = (blockIdx.x & 7) * TY;

    uint2*       s4 = (uint2*)smraw;
    const uint2* gb = (const uint2*)&g_blur[0];
    const int units_per_ch = (TY + 4) * 32;
    for (int u = tid; u < 10 * units_per_ch; u += 256) {
        int c   = u / units_per_ch;
        int rem = u - c * units_per_ch;
        int r   = rem >> 5;
        int xu  = rem & 31;
        int y   = y0 + r - 2;
        uint2 v = make_uint2(0u, 0u);
        if ((unsigned)y < (unsigned)DD)
            v = __ldcs(&gb[((c * VOL + ((z << 7) + y) * DD) >> 2) + xu]);
        s4[u] = v;
    }
    __syncthreads();

    int half_ = tid >> 7;
    int x     = tid & 127;
    double local = 0.0;

#pragma unroll 1
    for (int it = 0; it < TY / 2; it++) {
        int ry = it * 2 + half_;
        float val[10];
#pragma unroll
        for (int c = 0; c < 10; c++) val[c] = 0.f;
#pragma unroll
        for (int t = 0; t < 5; t++) {
            float k = c_gk[t];
            int r = ry + t;
#pragma unroll
            for (int c = 0; c < 10; c++)
                val[c] += k * __half2float(sin_[c * (TY + 4) * 128 + r * 128 + x]);
        }
#pragma unroll
        for (int c = 0; c < 10; c++) srow[c * 256 + half_ * 128 + x] = val[c];
        __syncthreads();

        float v[10];
#pragma unroll
        for (int c = 0; c < 10; c++) v[c] = 0.f;
#pragma unroll
        for (int t = 0; t < 5; t++) {
            int xx = x + t - 2;
            if ((unsigned)xx < (unsigned)DD) {
                float k = c_gk[t];
#pragma unroll
                for (int c = 0; c < 10; c++)
                    v[c] += k * srow[c * 256 + half_ * 128 + xx];
            }
        }
        float cr1 = v[2] - v[0] * v[1];
        float vI1 = fmaxf(v[3] - v[0] * v[0], 0.f) + 1e-5f;
        float vJ1 = fmaxf(v[4] - v[1] * v[1], 0.f) + 1e-5f;
        float cr2 = v[7] - v[5] * v[6];
        float vI2 = fmaxf(v[8] - v[5] * v[5], 0.f) + 1e-5f;
        float vJ2 = fmaxf(v[9] - v[6] * v[6], 0.f) + 1e-5f;
        local += (double)(1.0f - cr1 * rsqrtf(vI1 * vJ1))
               + (double)(1.0f - cr2 * rsqrtf(vI2 * vJ2));
        __syncthreads();
    }
    block_add(local, &g_acc[7]);
}

__global__ void k_final(float* __restrict__ out) {
    double ic    = g_acc[0] / (3.0 * (double)VOL);
    double dice1 = (2.0 * g_acc[1] + 1e-5) / (g_acc[2] + g_acc[3] + 1e-5);
    double dice2 = (2.0 * g_acc[4] + 1e-5) / (g_acc[5] + g_acc[6] + 1e-5);
    double dl    = (1.0 - dice1) + (1.0 - dice2);
    double sim   = g_acc[7] / (double)VOL;
    out[0] = (float)(128.0 * ic + sim + dl);
}

extern "C" void kernel_launch(void* const* d_in, const int* in_sizes, int n_in,
                              void* d_out, int out_size) {
    const float* phiAB = (const float*)d_in[0];
    const float* phiBA = (const float*)d_in[1];
    const float* imgA  = (const float*)d_in[2];
    const float* imgB  = (const float*)d_in[3];
    const float* labA  = (const float*)d_in[4];
    const float* labB  = (const float*)d_in[5];
    const float* noise = (const float*)d_in[6];
    float* out = (float*)d_out;

    static cudaStream_t s1 = nullptr;
    static cudaEvent_t evW, evB;
    if (s1 == nullptr) {
        cudaStreamCreateWithFlags(&s1, cudaStreamNonBlocking);
        cudaEventCreateWithFlags(&evW, cudaEventDisableTiming);
        cudaEventCreateWithFlags(&evB, cudaEventDisableTiming);
    }

    const int smem_yx = 10 * (TY + 4) * 128 * 2 + 10 * 2 * 128 * 4;  // 61,440 B
    cudaFuncSetAttribute(k_blurYX_red,
                         cudaFuncAttributeMaxDynamicSharedMemorySize, smem_yx);

    dim3 g(VOL / 256), b(256);

    // s0: init -> pack -> warpAB -> warpBA+mseF -> mseB -> (join) -> final
    // s1:                                      \-> blurZ -> blurYX
    k_init<<<1, 32>>>();
    k_pack<<<VOL / 1024, 256>>>(noise, imgA, labA, imgB, labB);
    k_warpAB<<<g, b>>>(phiAB, labB);
    k_warpBA_mseF<<<g, b>>>(phiBA, labA);
    cudaEventRecord(evW, 0);
    cudaStreamWaitEvent(s1, evW, 0);

    k_blurZ10<<<g, b, 0, s1>>>();
    k_blurYX_red<<<1024, 256, smem_yx, s1>>>();
    cudaEventRecord(evB, s1);

    k_mseB<<<g, b>>>(phiAB);
    cudaStreamWaitEvent(0, evB, 0);
    k_final<<<1, 1>>>(out);
}

// round 13
// speedup vs baseline: 1.0667x; 1.0667x over previous
#include <cuda_runtime.h>
#include <cuda_fp16.h>
#include <cuda_fp8.h>
#include <math.h>

#define DD  128
#define HW  16384            // 128*128
#define VOL 2097152          // 128^3
#define TY  16               // y-tile for blurYX
#define NSCI (1.0f / 32.0f)  // fp8 noise decode scale

struct __align__(16) h4p { __half2 a, b, c, d; };
struct __align__(8)  h4  { __half2 a, b; };

// ---- scratch (static device globals, allocation-free) ----
__device__ uint4        g_eA[VOL];         // 32 MB: paired (fp8 noise, imgA, labA)
__device__ uint4        g_eB[VOL];         // 32 MB: paired (fp8 noise, imgB, labB)
__device__ uint4        g_tmpFp[VOL];      // 32 MB: paired warp(Ieps, AB) fp16
__device__ uint4        g_tmpBp[VOL];      // 32 MB: paired warp(Ieps, BA) fp16
__device__ unsigned int g_n4[VOL];         //  8 MB: compact fp8 noise triple
__device__ __half2      g_W2[VOL];         //  8 MB: (WA, WB)
__device__ __half2      g_I2[VOL];         //  8 MB: (imgA, imgB)
__device__ __half       g_blur[10 * VOL];  // 40 MB: z-blurred channels
__device__ double       g_acc[16];

__constant__ float c_gk[5] = {
    0.05448868454964294f, 0.24420134200323332f, 0.40261995089424437f,
    0.24420134200323332f, 0.05448868454964294f };

__device__ __forceinline__ float idgv(int v) { return -1.0f + (float)v * (2.0f / 127.0f); }

__device__ __forceinline__ void axis_prep(float c, float& w0, float& w1, int& i0, int& i1) {
    float f  = floorf(c);
    float fr = c - f;
    int j0 = (int)f;
    w0 = (j0 >= 0 && j0 < DD)       ? (1.0f - fr) : 0.0f;
    w1 = (j0 >= -1 && j0 <= DD - 2) ? fr          : 0.0f;
    i0 = min(max(j0, 0), DD - 1);
    i1 = min(max(j0 + 1, 0), DD - 1);
}

__device__ __forceinline__ void axis_prep_pair(float c, float& pw0, float& pw1, int& base) {
    float f  = floorf(c);
    float fr = c - f;
    int j0 = (int)f;
    float w0 = (j0 >= 0 && j0 < DD)       ? (1.0f - fr) : 0.0f;
    float w1 = (j0 >= -1 && j0 <= DD - 2) ? fr          : 0.0f;
    if (j0 < 0) { pw0 = w1; pw1 = 0.0f; }
    else        { pw0 = w0; pw1 = w1;  }
    base = min(max(j0, 0), DD - 1);
}

struct AxesP {
    float wz[2], wy[2];
    int   iz[2], iy[2];
    float pwx0, pwx1;
    int   ixb;
};

__device__ __forceinline__ AxesP make_axesP(const float* __restrict__ phi, int i) {
    AxesP a;
    float z = (phi[i]           + 1.0f) * 63.5f;
    float y = (phi[VOL + i]     + 1.0f) * 63.5f;
    float x = (phi[2 * VOL + i] + 1.0f) * 63.5f;
    axis_prep(z, a.wz[0], a.wz[1], a.iz[0], a.iz[1]);
    axis_prep(y, a.wy[0], a.wy[1], a.iy[0], a.iy[1]);
    axis_prep_pair(x, a.pwx0, a.pwx1, a.ixb);
    return a;
}

__device__ __forceinline__ void dec_n3(unsigned int u0, float& n0, float& n1, float& n2) {
    __half2_raw h01 = __nv_cvt_fp8x2_to_halfraw2((__nv_fp8x2_storage_t)(u0 & 0xFFFFu), __NV_E4M3);
    __half2_raw h2r = __nv_cvt_fp8x2_to_halfraw2((__nv_fp8x2_storage_t)((u0 >> 16) & 0xFFFFu), __NV_E4M3);
    float2 f01 = __half22float2(*(__half2*)&h01);
    float2 f2  = __half22float2(*(__half2*)&h2r);
    n0 = f01.x; n1 = f01.y; n2 = f2.x;
}

struct F5 { float n0, n1, n2, img, lab; };

// 4 scattered LDG.128 over a paired e8 array (loop form — R9's proven shape)
__device__ __forceinline__ F5 gather_e8p(const uint4* __restrict__ src, const AxesP& a) {
    F5 r; r.n0 = r.n1 = r.n2 = r.img = r.lab = 0.f;
#pragma unroll
    for (int dz = 0; dz < 2; dz++) {
        int rz = a.iz[dz] * HW;
#pragma unroll
        for (int dy = 0; dy < 2; dy++) {
            float wzy = a.wz[dz] * a.wy[dy];
            float w0 = wzy * a.pwx0, w1 = wzy * a.pwx1;
            uint4 v = src[rz + a.iy[dy] * DD + a.ixb];
            float a0, a1, a2, b0, b1, b2;
            dec_n3(v.x, a0, a1, a2);
            dec_n3(v.z, b0, b1, b2);
            float2 ilA = __half22float2(*(__half2*)&v.y);
            float2 ilB = __half22float2(*(__half2*)&v.w);
            r.n0 += w0 * a0 + w1 * b0;
            r.n1 += w0 * a1 + w1 * b1;
            r.n2 += w0 * a2 + w1 * b2;
            r.img += w0 * ilA.x + w1 * ilB.x;
            r.lab += w0 * ilA.y + w1 * ilB.y;
        }
    }
    return r;
}

// 4 scattered LDG.128 over paired fp16 tmp arrays, 3 channels (loop form)
__device__ __forceinline__ float3 gather_h4p(const uint4* __restrict__ src, const AxesP& a) {
    float a0 = 0.f, a1 = 0.f, a2 = 0.f;
#pragma unroll
    for (int dz = 0; dz < 2; dz++) {
        int rz = a.iz[dz] * HW;
#pragma unroll
        for (int dy = 0; dy < 2; dy++) {
            float wzy = a.wz[dz] * a.wy[dy];
            float w0 = wzy * a.pwx0, w1 = wzy * a.pwx1;
            uint4 vr = src[rz + a.iy[dy] * DD + a.ixb];
            h4p v = *(h4p*)&vr;
            float2 p0 = __half22float2(v.a);
            float  q0 = __half2float(v.b.x);
            float2 p1 = __half22float2(v.c);
            float  q1 = __half2float(v.d.x);
            a0 += w0 * p0.x + w1 * p1.x;
            a1 += w0 * p0.y + w1 * p1.y;
            a2 += w0 * q0   + w1 * q1;
        }
    }
    return make_float3(a0, a1, a2);
}

__device__ __forceinline__ float3 warp_idgP(const AxesP& a) {
    float Sz0 = a.wz[0] + a.wz[1];
    float Sy0 = a.wy[0] + a.wy[1];
    float Sx0 = a.pwx0 + a.pwx1;
    float Sz1 = a.wz[0] * idgv(a.iz[0]) + a.wz[1] * idgv(a.iz[1]);
    float Sy1 = a.wy[0] * idgv(a.iy[0]) + a.wy[1] * idgv(a.iy[1]);
    float Sx1 = a.pwx0 * idgv(a.ixb) + a.pwx1 * idgv(min(a.ixb + 1, DD - 1));
    return make_float3(Sz1 * Sy0 * Sx0, Sz0 * Sy1 * Sx0, Sz0 * Sy0 * Sx1);
}

__device__ __forceinline__ void block_add(double v, double* dst) {
    __shared__ double sm[8];
    int lane = threadIdx.x & 31;
    int wid  = threadIdx.x >> 5;
#pragma unroll
    for (int o = 16; o > 0; o >>= 1) v += __shfl_down_sync(0xffffffffu, v, o);
    __syncthreads();
    if (lane == 0) sm[wid] = v;
    __syncthreads();
    if (wid == 0) {
        double t = (lane < 8) ? sm[lane] : 0.0;
#pragma unroll
        for (int o = 4; o > 0; o >>= 1) t += __shfl_down_sync(0xffffffffu, t, o);
        if (lane == 0) atomicAdd(dst, t);
    }
}

// two reductions sharing one sync pair
__device__ __forceinline__ void block_add2(double v0, double v1, double* d0, double* d1) {
    __shared__ double sm2[2][8];
    int lane = threadIdx.x & 31;
    int wid  = threadIdx.x >> 5;
#pragma unroll
    for (int o = 16; o > 0; o >>= 1) {
        v0 += __shfl_down_sync(0xffffffffu, v0, o);
        v1 += __shfl_down_sync(0xffffffffu, v1, o);
    }
    __syncthreads();
    if (lane == 0) { sm2[0][wid] = v0; sm2[1][wid] = v1; }
    __syncthreads();
    if (wid == 0) {
        double t0 = (lane < 8) ? sm2[0][lane] : 0.0;
        double t1 = (lane < 8) ? sm2[1][lane] : 0.0;
#pragma unroll
        for (int o = 4; o > 0; o >>= 1) {
            t0 += __shfl_down_sync(0xffffffffu, t0, o);
            t1 += __shfl_down_sync(0xffffffffu, t1, o);
        }
        if (lane == 0) { atomicAdd(d0, t0); atomicAdd(d1, t1); }
    }
}

__global__ void k_init() {
    if (threadIdx.x < 16) g_acc[threadIdx.x] = 0.0;
}

// pack: paired e8 arrays (smem-staged), n4, I2, dice denominators. 4 vox/thread.
__global__ void k_pack(const float* __restrict__ noise,
                       const float* __restrict__ imgA, const float* __restrict__ labA,
                       const float* __restrict__ imgB, const float* __restrict__ labB) {
    __shared__ uint2 sA[1024], sB[1024];
    int tid = threadIdx.x;
    int base = blockIdx.x * 1024;
    int l0 = tid * 4;
    int i4 = base + l0;

    float4 n0 = __ldcs((const float4*)&noise[i4]);
    float4 n1 = __ldcs((const float4*)&noise[VOL + i4]);
    float4 n2 = __ldcs((const float4*)&noise[2 * VOL + i4]);
    float4 ia = __ldcs((const float4*)&imgA[i4]);
    float4 la = __ldcs((const float4*)&labA[i4]);
    float4 ib = __ldcs((const float4*)&imgB[i4]);
    float4 lb = __ldcs((const float4*)&labB[i4]);

    const float* pn0 = &n0.x; const float* pn1 = &n1.x; const float* pn2 = &n2.x;
    const float* pia = &ia.x; const float* pla = &la.x;
    const float* pib = &ib.x; const float* plb = &lb.x;

#pragma unroll
    for (int k = 0; k < 4; k++) {
        unsigned int b0 = (unsigned int)__nv_cvt_float_to_fp8(pn0[k] * 0.25f, __NV_SATFINITE, __NV_E4M3);
        unsigned int b1 = (unsigned int)__nv_cvt_float_to_fp8(pn1[k] * 0.25f, __NV_SATFINITE, __NV_E4M3);
        unsigned int b2 = (unsigned int)__nv_cvt_float_to_fp8(pn2[k] * 0.25f, __NV_SATFINITE, __NV_E4M3);
        unsigned int u0 = b0 | (b1 << 8) | (b2 << 16);
        __half2 hA = __floats2half2_rn(pia[k], pla[k]);
        __half2 hB = __floats2half2_rn(pib[k], plb[k]);
        sA[l0 + k] = make_uint2(u0, *(unsigned int*)&hA);
        sB[l0 + k] = make_uint2(u0, *(unsigned int*)&hB);
        g_n4[i4 + k] = u0;
        g_I2[i4 + k] = __floats2half2_rn(pia[k], pib[k]);
    }
    __syncthreads();

#pragma unroll
    for (int k = 0; k < 4; k++) {
        int l = l0 + k;
        int gi = base + l;
        int nb = ((gi & 127) < 127) ? l + 1 : l;
        uint2 a0 = sA[l], a1 = sA[nb];
        uint2 c0 = sB[l], c1 = sB[nb];
        g_eA[gi] = make_uint4(a0.x, a0.y, a1.x, a1.y);
        g_eB[gi] = make_uint4(c0.x, c0.y, c1.x, c1.y);
    }

    double slb = (double)lb.x + (double)lb.y + (double)lb.z + (double)lb.w;
    double sla = (double)la.x + (double)la.y + (double)la.z + (double)la.w;
    block_add2(slb, sla, &g_acc[3], &g_acc[6]);
}

// both directions fused (R9 shape): Ieps warps + sim/label warps + dice numerators
__global__ void __launch_bounds__(256) k_warp_all(
        const float* __restrict__ phiAB, const float* __restrict__ phiBA,
        const float* __restrict__ labA, const float* __restrict__ labB) {
    __shared__ h4 bufF[256], bufB[256];
    int tid = threadIdx.x;
    int i = blockIdx.x * 256 + tid;

    AxesP aAB = make_axesP(phiAB, i);
    AxesP aBA = make_axesP(phiBA, i);

    F5 fA = gather_e8p(g_eA, aAB);   // noise + imgA + labA via AB
    F5 fB = gather_e8p(g_eB, aBA);   // noise + imgB + labB via BA
    float3 gA = warp_idgP(aAB);
    float3 gB = warp_idgP(aBA);

    bufF[tid].a = __floats2half2_rn(gA.x + fA.n0 * NSCI, gA.y + fA.n1 * NSCI);
    bufF[tid].b = __floats2half2_rn(gA.z + fA.n2 * NSCI, 0.0f);
    bufB[tid].a = __floats2half2_rn(gB.x + fB.n0 * NSCI, gB.y + fB.n1 * NSCI);
    bufB[tid].b = __floats2half2_rn(gB.z + fB.n2 * NSCI, 0.0f);
    __syncthreads();

    int dn = ((tid & 127) < 127) ? 1 : 0;
    { h4 s0 = bufF[tid], s1 = bufF[tid + dn];
      g_tmpFp[i] = make_uint4(*(unsigned int*)&s0.a, *(unsigned int*)&s0.b,
                              *(unsigned int*)&s1.a, *(unsigned int*)&s1.b); }
    { h4 s0 = bufB[tid], s1 = bufB[tid + dn];
      g_tmpBp[i] = make_uint4(*(unsigned int*)&s0.a, *(unsigned int*)&s0.b,
                              *(unsigned int*)&s1.a, *(unsigned int*)&s1.b); }

    g_W2[i] = __floats2half2_rn(fA.img, fB.img);

    block_add2((double)(fA.lab * labB[i]), (double)fA.lab, &g_acc[1], &g_acc[2]);
    block_add2((double)(fB.lab * labA[i]), (double)fB.lab, &g_acc[4], &g_acc[5]);
}

// fused MSE both directions (R9 shape); Ieps noise from compact g_n4
__global__ void __launch_bounds__(256) k_mse_both(
        const float* __restrict__ phiAB, const float* __restrict__ phiBA) {
    int i = blockIdx.x * 256 + threadIdx.x;
    AxesP aBA = make_axesP(phiBA, i);
    AxesP aAB = make_axesP(phiAB, i);
    float3 f = gather_h4p(g_tmpFp, aBA);
    float3 b = gather_h4p(g_tmpBp, aAB);

    float n0, n1, n2;
    dec_n3(g_n4[i], n0, n1, n2);
    int zz = i >> 14, yy = (i >> 7) & 127, xx = i & 127;
    float e0 = idgv(zz) + n0 * NSCI;
    float e1 = idgv(yy) + n1 * NSCI;
    float e2 = idgv(xx) + n2 * NSCI;

    float d0 = e0 - f.x, d1 = e1 - f.y, d2 = e2 - f.z;
    float c0 = e0 - b.x, c1 = e1 - b.y, c2 = e2 - b.z;
    double s = (double)(d0*d0) + (double)(d1*d1) + (double)(d2*d2)
             + (double)(c0*c0) + (double)(c1*c1) + (double)(c2*c2);
    block_add(s, &g_acc[0]);
}

// z-blur; streaming stores so co-run with mse doesn't evict gather arrays
__global__ void k_blurZ10() {
    int i = blockIdx.x * 256 + threadIdx.x;
    int z = i >> 14;
    float a[10];
#pragma unroll
    for (int c = 0; c < 10; c++) a[c] = 0.f;
#pragma unroll
    for (int t = 0; t < 5; t++) {
        int zz = z + t - 2;
        if ((unsigned)zz < (unsigned)DD) {
            int off = i + (t - 2) * HW;
            float k = c_gk[t];
            float2 w2 = __half22float2(g_W2[off]);
            float2 ij = __half22float2(g_I2[off]);
            float wa = w2.x, wb = w2.y, ia = ij.x, jb = ij.y;
            a[0] += k * wa;      a[1] += k * jb;
            a[2] += k * wa * jb; a[3] += k * wa * wa; a[4] += k * jb * jb;
            a[5] += k * ia;      a[6] += k * wb;
            a[7] += k * ia * wb; a[8] += k * ia * ia; a[9] += k * wb * wb;
        }
    }
#pragma unroll
    for (int c = 0; c < 10; c++) __stcs(&g_blur[c * VOL + i], __float2half_rn(a[c]));
}

__global__ void k_blurYX_red() {
    extern __shared__ char smraw[];
    __half* sin_ = (__half*)smraw;
    float*  srow = (float*)(smraw + 10 * (TY + 4) * 128 * 2);

    int tid = threadIdx.x;
    int z   = blockIdx.x >> 3;
    int y0  = (blockIdx.x & 7) * TY;

    uint2*       s4 = (uint2*)smraw;
    const uint2* gb = (const uint2*)&g_blur[0];
    const int units_per_ch = (TY + 4) * 32;
    for (int u = tid; u < 10 * units_per_ch; u += 256) {
        int c   = u / units_per_ch;
        int rem = u - c * units_per_ch;
        int r   = rem >> 5;
        int xu  = rem & 31;
        int y   = y0 + r - 2;
        uint2 v = make_uint2(0u, 0u);
        if ((unsigned)y < (unsigned)DD)
            v = __ldcs(&gb[((c * VOL + ((z << 7) + y) * DD) >> 2) + xu]);
        s4[u] = v;
    }
    __syncthreads();

    int half_ = tid >> 7;
    int x     = tid & 127;
    double local = 0.0;

#pragma unroll 1
    for (int it = 0; it < TY / 2; it++) {
        int ry = it * 2 + half_;
        float val[10];
#pragma unroll
        for (int c = 0; c < 10; c++) val[c] = 0.f;
#pragma unroll
        for (int t = 0; t < 5; t++) {
            float k = c_gk[t];
            int r = ry + t;
#pragma unroll
            for (int c = 0; c < 10; c++)
                val[c] += k * __half2float(sin_[c * (TY + 4) * 128 + r * 128 + x]);
        }
#pragma unroll
        for (int c = 0; c < 10; c++) srow[c * 256 + half_ * 128 + x] = val[c];
        __syncthreads();

        float v[10];
#pragma unroll
        for (int c = 0; c < 10; c++) v[c] = 0.f;
#pragma unroll
        for (int t = 0; t < 5; t++) {
            int xx = x + t - 2;
            if ((unsigned)xx < (unsigned)DD) {
                float k = c_gk[t];
#pragma unroll
                for (int c = 0; c < 10; c++)
                    v[c] += k * srow[c * 256 + half_ * 128 + xx];
            }
        }
        float cr1 = v[2] - v[0] * v[1];
        float vI1 = fmaxf(v[3] - v[0] * v[0], 0.f) + 1e-5f;
        float vJ1 = fmaxf(v[4] - v[1] * v[1], 0.f) + 1e-5f;
        float cr2 = v[7] - v[5] * v[6];
        float vI2 = fmaxf(v[8] - v[5] * v[5], 0.f) + 1e-5f;
        float vJ2 = fmaxf(v[9] - v[6] * v[6], 0.f) + 1e-5f;
        local += (double)(1.0f - cr1 * rsqrtf(vI1 * vJ1))
               + (double)(1.0f - cr2 * rsqrtf(vI2 * vJ2));
        __syncthreads();
    }
    block_add(local, &g_acc[7]);
}

__global__ void k_final(float* __restrict__ out) {
    double ic    = g_acc[0] / (3.0 * (double)VOL);
    double dice1 = (2.0 * g_acc[1] + 1e-5) / (g_acc[2] + g_acc[3] + 1e-5);
    double dice2 = (2.0 * g_acc[4] + 1e-5) / (g_acc[5] + g_acc[6] + 1e-5);
    double dl    = (1.0 - dice1) + (1.0 - dice2);
    double sim   = g_acc[7] / (double)VOL;
    out[0] = (float)(128.0 * ic + sim + dl);
}

extern "C" void kernel_launch(void* const* d_in, const int* in_sizes, int n_in,
                              void* d_out, int out_size) {
    const float* phiAB = (const float*)d_in[0];
    const float* phiBA = (const float*)d_in[1];
    const float* imgA  = (const float*)d_in[2];
    const float* imgB  = (const float*)d_in[3];
    const float* labA  = (const float*)d_in[4];
    const float* labB  = (const float*)d_in[5];
    const float* noise = (const float*)d_in[6];
    float* out = (float*)d_out;

    static cudaStream_t s1 = nullptr;
    static cudaEvent_t evW, evB;
    if (s1 == nullptr) {
        cudaStreamCreateWithFlags(&s1, cudaStreamNonBlocking);
        cudaEventCreateWithFlags(&evW, cudaEventDisableTiming);
        cudaEventCreateWithFlags(&evB, cudaEventDisableTiming);
    }

    const int smem_yx = 10 * (TY + 4) * 128 * 2 + 10 * 2 * 128 * 4;  // 61,440 B
    cudaFuncSetAttribute(k_blurYX_red,
                         cudaFuncAttributeMaxDynamicSharedMemorySize, smem_yx);

    dim3 g(VOL / 256), b(256);

    // s0: init -> pack -> warp_all -> mse_both -> (join) -> final
    // s1:                        \-> blurZ -> blurYX
    k_init<<<1, 32>>>();
    k_pack<<<VOL / 1024, 256>>>(noise, imgA, labA, imgB, labB);
    k_warp_all<<<g, b>>>(phiAB, phiBA, labA, labB);
    cudaEventRecord(evW, 0);
    cudaStreamWaitEvent(s1, evW, 0);

    k_mse_both<<<g, b>>>(phiAB, phiBA);    // starts immediately on s0

    k_blurZ10<<<g, b, 0, s1>>>();
    k_blurYX_red<<<1024, 256, smem_yx, s1>>>();
    cudaEventRecord(evB, s1);

    cudaStreamWaitEvent(0, evB, 0);
    k_final<<<1, 1>>>(out);
}

// round 14
// speedup vs baseline: 1.1332x; 1.0623x over previous
#include <cuda_runtime.h>
#include <cuda_fp16.h>
#include <cuda_fp8.h>
#include <math.h>

#define DD  128
#define HW  16384            // 128*128
#define VOL 2097152          // 128^3
#define TY  16               // y-tile for blurYX
#define NSCI (1.0f / 32.0f)  // fp8 noise decode scale

struct __align__(16) h4p { __half2 a, b, c, d; };
struct __align__(8)  h4  { __half2 a, b; };

// ---- scratch (static device globals, allocation-free) ----
// combined element (8B): u0 = n0|n1<<8|n2<<16|imgA<<24 (all fp8; noise scaled x32)
//                        u1 = labA|imgB<<8|labB<<16    (fp8)
// stored x-paired: uint4 = {self.u0, self.u1, next.u0, next.u1}
__device__ uint4   g_e[VOL];          // 32 MB: ONE gather array for both directions
__device__ uint4   g_tmpFp[VOL];      // 32 MB: paired warp(Ieps, AB) fp16
__device__ uint4   g_tmpBp[VOL];      // 32 MB: paired warp(Ieps, BA) fp16
__device__ __half2 g_W2[VOL];         //  8 MB: (WA, WB)
__device__ __half2 g_I2[VOL];         //  8 MB: (imgA, imgB) fp16 (blur inputs)
__device__ __half  g_blur[10 * VOL];  // 40 MB: z-blurred channels
__device__ double  g_acc[16];

__constant__ float c_gk[5] = {
    0.05448868454964294f, 0.24420134200323332f, 0.40261995089424437f,
    0.24420134200323332f, 0.05448868454964294f };

__device__ __forceinline__ float idgv(int v) { return -1.0f + (float)v * (2.0f / 127.0f); }

__device__ __forceinline__ void axis_prep(float c, float& w0, float& w1, int& i0, int& i1) {
    float f  = floorf(c);
    float fr = c - f;
    int j0 = (int)f;
    w0 = (j0 >= 0 && j0 < DD)       ? (1.0f - fr) : 0.0f;
    w1 = (j0 >= -1 && j0 <= DD - 2) ? fr          : 0.0f;
    i0 = min(max(j0, 0), DD - 1);
    i1 = min(max(j0 + 1, 0), DD - 1);
}

__device__ __forceinline__ void axis_prep_pair(float c, float& pw0, float& pw1, int& base) {
    float f  = floorf(c);
    float fr = c - f;
    int j0 = (int)f;
    float w0 = (j0 >= 0 && j0 < DD)       ? (1.0f - fr) : 0.0f;
    float w1 = (j0 >= -1 && j0 <= DD - 2) ? fr          : 0.0f;
    if (j0 < 0) { pw0 = w1; pw1 = 0.0f; }
    else        { pw0 = w0; pw1 = w1;  }
    base = min(max(j0, 0), DD - 1);
}

struct AxesP {
    float wz[2], wy[2];
    int   iz[2], iy[2];
    float pwx0, pwx1;
    int   ixb;
};

__device__ __forceinline__ AxesP make_axesP(const float* __restrict__ phi, int i) {
    AxesP a;
    float z = (phi[i]           + 1.0f) * 63.5f;
    float y = (phi[VOL + i]     + 1.0f) * 63.5f;
    float x = (phi[2 * VOL + i] + 1.0f) * 63.5f;
    axis_prep(z, a.wz[0], a.wz[1], a.iz[0], a.iz[1]);
    axis_prep(y, a.wy[0], a.wy[1], a.iy[0], a.iy[1]);
    axis_prep_pair(x, a.pwx0, a.pwx1, a.ixb);
    return a;
}

__device__ __forceinline__ float fp8x2_lo(unsigned int u16_, float& hi) {
    __half2_raw h = __nv_cvt_fp8x2_to_halfraw2((__nv_fp8x2_storage_t)(u16_ & 0xFFFFu), __NV_E4M3);
    float2 f = __half22float2(*(__half2*)&h);
    hi = f.y;
    return f.x;
}

struct F5 { float n0, n1, n2, img, lab; };

// decode one combined element for direction ISB (0=A, 1=B)
template <int ISB>
__device__ __forceinline__ void dec_c(unsigned int u0, unsigned int u1,
                                      float& n0, float& n1, float& n2,
                                      float& img, float& lab) {
    float t1, t3, t5;
    n0 = fp8x2_lo(u0, t1);            n1 = t1;          // bytes 0,1
    n2 = fp8x2_lo(u0 >> 16, t3);                        // bytes 2,3: n2, imgA
    float lA = fp8x2_lo(u1, t5);                        // bytes 0,1: labA, imgB
    if (ISB) {
        float dummy;
        img = t5;                                       // imgB
        lab = fp8x2_lo(u1 >> 16, dummy);                // labB
    } else {
        img = t3;                                       // imgA
        lab = lA;                                       // labA
    }
}

// 4 scattered LDG.128 over the combined paired array (loop form — R9 shape)
template <int ISB>
__device__ __forceinline__ F5 gather_c(const uint4* __restrict__ src, const AxesP& a) {
    F5 r; r.n0 = r.n1 = r.n2 = r.img = r.lab = 0.f;
#pragma unroll
    for (int dz = 0; dz < 2; dz++) {
        int rz = a.iz[dz] * HW;
#pragma unroll
        for (int dy = 0; dy < 2; dy++) {
            float wzy = a.wz[dz] * a.wy[dy];
            float w0 = wzy * a.pwx0, w1 = wzy * a.pwx1;
            uint4 v = src[rz + a.iy[dy] * DD + a.ixb];
            float a0, a1, a2, ai, al, b0, b1, b2, bi, bl;
            dec_c<ISB>(v.x, v.y, a0, a1, a2, ai, al);
            dec_c<ISB>(v.z, v.w, b0, b1, b2, bi, bl);
            r.n0 += w0 * a0 + w1 * b0;
            r.n1 += w0 * a1 + w1 * b1;
            r.n2 += w0 * a2 + w1 * b2;
            r.img += w0 * ai + w1 * bi;
            r.lab += w0 * al + w1 * bl;
        }
    }
    return r;
}

// 4 scattered LDG.128 over paired fp16 tmp arrays, 3 channels (loop form)
__device__ __forceinline__ float3 gather_h4p(const uint4* __restrict__ src, const AxesP& a) {
    float a0 = 0.f, a1 = 0.f, a2 = 0.f;
#pragma unroll
    for (int dz = 0; dz < 2; dz++) {
        int rz = a.iz[dz] * HW;
#pragma unroll
        for (int dy = 0; dy < 2; dy++) {
            float wzy = a.wz[dz] * a.wy[dy];
            float w0 = wzy * a.pwx0, w1 = wzy * a.pwx1;
            uint4 vr = src[rz + a.iy[dy] * DD + a.ixb];
            h4p v = *(h4p*)&vr;
            float2 p0 = __half22float2(v.a);
            float  q0 = __half2float(v.b.x);
            float2 p1 = __half22float2(v.c);
            float  q1 = __half2float(v.d.x);
            a0 += w0 * p0.x + w1 * p1.x;
            a1 += w0 * p0.y + w1 * p1.y;
            a2 += w0 * q0   + w1 * q1;
        }
    }
    return make_float3(a0, a1, a2);
}

__device__ __forceinline__ float3 warp_idgP(const AxesP& a) {
    float Sz0 = a.wz[0] + a.wz[1];
    float Sy0 = a.wy[0] + a.wy[1];
    float Sx0 = a.pwx0 + a.pwx1;
    float Sz1 = a.wz[0] * idgv(a.iz[0]) + a.wz[1] * idgv(a.iz[1]);
    float Sy1 = a.wy[0] * idgv(a.iy[0]) + a.wy[1] * idgv(a.iy[1]);
    float Sx1 = a.pwx0 * idgv(a.ixb) + a.pwx1 * idgv(min(a.ixb + 1, DD - 1));
    return make_float3(Sz1 * Sy0 * Sx0, Sz0 * Sy1 * Sx0, Sz0 * Sy0 * Sx1);
}

__device__ __forceinline__ void block_add(double v, double* dst) {
    __shared__ double sm[8];
    int lane = threadIdx.x & 31;
    int wid  = threadIdx.x >> 5;
#pragma unroll
    for (int o = 16; o > 0; o >>= 1) v += __shfl_down_sync(0xffffffffu, v, o);
    __syncthreads();
    if (lane == 0) sm[wid] = v;
    __syncthreads();
    if (wid == 0) {
        double t = (lane < 8) ? sm[lane] : 0.0;
#pragma unroll
        for (int o = 4; o > 0; o >>= 1) t += __shfl_down_sync(0xffffffffu, t, o);
        if (lane == 0) atomicAdd(dst, t);
    }
}

__global__ void k_init() {
    if (threadIdx.x < 16) g_acc[threadIdx.x] = 0.0;
}

__device__ __forceinline__ unsigned int f2fp8(float v) {
    return (unsigned int)__nv_cvt_float_to_fp8(v, __NV_SATFINITE, __NV_E4M3);
}

// pack: combined paired array (smem-staged), I2, dice denominators. 4 vox/thread.
__global__ void k_pack(const float* __restrict__ noise,
                       const float* __restrict__ imgA, const float* __restrict__ labA,
                       const float* __restrict__ imgB, const float* __restrict__ labB) {
    __shared__ uint2 sE[1024];
    int tid = threadIdx.x;
    int base = blockIdx.x * 1024;
    int l0 = tid * 4;
    int i4 = base + l0;

    float4 n0 = *(const float4*)&noise[i4];
    float4 n1 = *(const float4*)&noise[VOL + i4];
    float4 n2 = *(const float4*)&noise[2 * VOL + i4];
    float4 ia = *(const float4*)&imgA[i4];
    float4 la = *(const float4*)&labA[i4];
    float4 ib = *(const float4*)&imgB[i4];
    float4 lb = *(const float4*)&labB[i4];

    const float* pn0 = &n0.x; const float* pn1 = &n1.x; const float* pn2 = &n2.x;
    const float* pia = &ia.x; const float* pla = &la.x;
    const float* pib = &ib.x; const float* plb = &lb.x;

#pragma unroll
    for (int k = 0; k < 4; k++) {
        unsigned int u0 = f2fp8(pn0[k] * 0.25f)
                        | (f2fp8(pn1[k] * 0.25f) << 8)
                        | (f2fp8(pn2[k] * 0.25f) << 16)
                        | (f2fp8(pia[k]) << 24);
        unsigned int u1 = f2fp8(pla[k])
                        | (f2fp8(pib[k]) << 8)
                        | (f2fp8(plb[k]) << 16);
        sE[l0 + k] = make_uint2(u0, u1);
        g_I2[i4 + k] = __floats2half2_rn(pia[k], pib[k]);
    }
    __syncthreads();

#pragma unroll
    for (int k = 0; k < 4; k++) {
        int l = l0 + k;
        int gi = base + l;
        int nb = ((gi & 127) < 127) ? l + 1 : l;
        uint2 e0 = sE[l], e1 = sE[nb];
        g_e[gi] = make_uint4(e0.x, e0.y, e1.x, e1.y);
    }

    double slb = (double)lb.x + (double)lb.y + (double)lb.z + (double)lb.w;
    double sla = (double)la.x + (double)la.y + (double)la.z + (double)la.w;
    block_add(slb, &g_acc[3]);
    block_add(sla, &g_acc[6]);
}

// both directions fused (R9 shape); single 32MB gather array
__global__ void __launch_bounds__(256) k_warp_all(
        const float* __restrict__ phiAB, const float* __restrict__ phiBA,
        const float* __restrict__ labA, const float* __restrict__ labB) {
    __shared__ h4 buf[256];
    int tid = threadIdx.x;
    int i = blockIdx.x * 256 + tid;

    AxesP aAB = make_axesP(phiAB, i);
    AxesP aBA = make_axesP(phiBA, i);

    F5 fA = gather_c<0>(g_e, aAB);   // noise + imgA + labA via AB
    F5 fB = gather_c<1>(g_e, aBA);   // noise + imgB + labB via BA
    float3 gA = warp_idgP(aAB);
    float3 gB = warp_idgP(aBA);

    int dn = ((tid & 127) < 127) ? 1 : 0;

    buf[tid].a = __floats2half2_rn(gA.x + fA.n0 * NSCI, gA.y + fA.n1 * NSCI);
    buf[tid].b = __floats2half2_rn(gA.z + fA.n2 * NSCI, 0.0f);
    __syncthreads();
    { h4 s0 = buf[tid], s1 = buf[tid + dn];
      g_tmpFp[i] = make_uint4(*(unsigned int*)&s0.a, *(unsigned int*)&s0.b,
                              *(unsigned int*)&s1.a, *(unsigned int*)&s1.b); }
    __syncthreads();
    buf[tid].a = __floats2half2_rn(gB.x + fB.n0 * NSCI, gB.y + fB.n1 * NSCI);
    buf[tid].b = __floats2half2_rn(gB.z + fB.n2 * NSCI, 0.0f);
    __syncthreads();
    { h4 s0 = buf[tid], s1 = buf[tid + dn];
      g_tmpBp[i] = make_uint4(*(unsigned int*)&s0.a, *(unsigned int*)&s0.b,
                              *(unsigned int*)&s1.a, *(unsigned int*)&s1.b); }

    g_W2[i] = __floats2half2_rn(fA.img, fB.img);

    block_add((double)(fA.lab * labB[i]), &g_acc[1]);
    block_add((double)fA.lab,             &g_acc[2]);
    block_add((double)(fB.lab * labA[i]), &g_acc[4]);
    block_add((double)fB.lab,             &g_acc[5]);
}

// fused MSE both directions (R9 shape); Ieps noise from g_e[i] bytes 0-2
__global__ void __launch_bounds__(256) k_mse_both(
        const float* __restrict__ phiAB, const float* __restrict__ phiBA) {
    int i = blockIdx.x * 256 + threadIdx.x;
    AxesP aBA = make_axesP(phiBA, i);
    AxesP aAB = make_axesP(phiAB, i);
    float3 f = gather_h4p(g_tmpFp, aBA);
    float3 b = gather_h4p(g_tmpBp, aAB);

    unsigned int u0 = g_e[i].x;
    float n1d, n3d;
    float n0 = fp8x2_lo(u0, n1d);
    float n2 = fp8x2_lo(u0 >> 16, n3d);
    int zz = i >> 14, yy = (i >> 7) & 127, xx = i & 127;
    float e0 = idgv(zz) + n0  * NSCI;
    float e1 = idgv(yy) + n1d * NSCI;
    float e2 = idgv(xx) + n2  * NSCI;

    float d0 = e0 - f.x, d1 = e1 - f.y, d2 = e2 - f.z;
    float c0 = e0 - b.x, c1 = e1 - b.y, c2 = e2 - b.z;
    double s = (double)(d0*d0) + (double)(d1*d1) + (double)(d2*d2)
             + (double)(c0*c0) + (double)(c1*c1) + (double)(c2*c2);
    block_add(s, &g_acc[0]);
}

// z-blur; streaming stores so co-run with mse doesn't evict gather arrays
__global__ void k_blurZ10() {
    int i = blockIdx.x * 256 + threadIdx.x;
    int z = i >> 14;
    float a[10];
#pragma unroll
    for (int c = 0; c < 10; c++) a[c] = 0.f;
#pragma unroll
    for (int t = 0; t < 5; t++) {
        int zz = z + t - 2;
        if ((unsigned)zz < (unsigned)DD) {
            int off = i + (t - 2) * HW;
            float k = c_gk[t];
            float2 w2 = __half22float2(g_W2[off]);
            float2 ij = __half22float2(g_I2[off]);
            float wa = w2.x, wb = w2.y, ia = ij.x, jb = ij.y;
            a[0] += k * wa;      a[1] += k * jb;
            a[2] += k * wa * jb; a[3] += k * wa * wa; a[4] += k * jb * jb;
            a[5] += k * ia;      a[6] += k * wb;
            a[7] += k * ia * wb; a[8] += k * ia * ia; a[9] += k * wb * wb;
        }
    }
#pragma unroll
    for (int c = 0; c < 10; c++) __stcs(&g_blur[c * VOL + i], __float2half_rn(a[c]));
}

__global__ void k_blurYX_red() {
    extern __shared__ char smraw[];
    __half* sin_ = (__half*)smraw;
    float*  srow = (float*)(smraw + 10 * (TY + 4) * 128 * 2);

    int tid = threadIdx.x;
    int z   = blockIdx.x >> 3;
    int y0  = (blockIdx.x & 7) * TY;

    uint2*       s4 = (uint2*)smraw;
    const uint2* gb = (const uint2*)&g_blur[0];
    const int units_per_ch = (TY + 4) * 32;
    for (int u = tid; u < 10 * units_per_ch; u += 256) {
        int c   = u / units_per_ch;
        int rem = u - c * units_per_ch;
        int r   = rem >> 5;
        int xu  = rem & 31;
        int y   = y0 + r - 2;
        uint2 v = make_uint2(0u, 0u);
        if ((unsigned)y < (unsigned)DD)
            v = __ldcs(&gb[((c * VOL + ((z << 7) + y) * DD) >> 2) + xu]);
        s4[u] = v;
    }
    __syncthreads();

    int half_ = tid >> 7;
    int x     = tid & 127;
    double local = 0.0;

#pragma unroll 1
    for (int it = 0; it < TY / 2; it++) {
        int ry = it * 2 + half_;
        float val[10];
#pragma unroll
        for (int c = 0; c < 10; c++) val[c] = 0.f;
#pragma unroll
        for (int t = 0; t < 5; t++) {
            float k = c_gk[t];
            int r = ry + t;
#pragma unroll
            for (int c = 0; c < 10; c++)
                val[c] += k * __half2float(sin_[c * (TY + 4) * 128 + r * 128 + x]);
        }
#pragma unroll
        for (int c = 0; c < 10; c++) srow[c * 256 + half_ * 128 + x] = val[c];
        __syncthreads();

        float v[10];
#pragma unroll
        for (int c = 0; c < 10; c++) v[c] = 0.f;
#pragma unroll
        for (int t = 0; t < 5; t++) {
            int xx = x + t - 2;
            if ((unsigned)xx < (unsigned)DD) {
                float k = c_gk[t];
#pragma unroll
                for (int c = 0; c < 10; c++)
                    v[c] += k * srow[c * 256 + half_ * 128 + xx];
            }
        }
        float cr1 = v[2] - v[0] * v[1];
        float vI1 = fmaxf(v[3] - v[0] * v[0], 0.f) + 1e-5f;
        float vJ1 = fmaxf(v[4] - v[1] * v[1], 0.f) + 1e-5f;
        float cr2 = v[7] - v[5] * v[6];
        float vI2 = fmaxf(v[8] - v[5] * v[5], 0.f) + 1e-5f;
        float vJ2 = fmaxf(v[9] - v[6] * v[6], 0.f) + 1e-5f;
        local += (double)(1.0f - cr1 * rsqrtf(vI1 * vJ1))
               + (double)(1.0f - cr2 * rsqrtf(vI2 * vJ2));
        __syncthreads();
    }
    block_add(local, &g_acc[7]);
}

__global__ void k_final(float* __restrict__ out) {
    double ic    = g_acc[0] / (3.0 * (double)VOL);
    double dice1 = (2.0 * g_acc[1] + 1e-5) / (g_acc[2] + g_acc[3] + 1e-5);
    double dice2 = (2.0 * g_acc[4] + 1e-5) / (g_acc[5] + g_acc[6] + 1e-5);
    double dl    = (1.0 - dice1) + (1.0 - dice2);
    double sim   = g_acc[7] / (double)VOL;
    out[0] = (float)(128.0 * ic + sim + dl);
}

extern "C" void kernel_launch(void* const* d_in, const int* in_sizes, int n_in,
                              void* d_out, int out_size) {
    const float* phiAB = (const float*)d_in[0];
    const float* phiBA = (const float*)d_in[1];
    const float* imgA  = (const float*)d_in[2];
    const float* imgB  = (const float*)d_in[3];
    const float* labA  = (const float*)d_in[4];
    const float* labB  = (const float*)d_in[5];
    const float* noise = (const float*)d_in[6];
    float* out = (float*)d_out;

    static cudaStream_t s1 = nullptr;
    static cudaEvent_t evW, evB;
    if (s1 == nullptr) {
        cudaStreamCreateWithFlags(&s1, cudaStreamNonBlocking);
        cudaEventCreateWithFlags(&evW, cudaEventDisableTiming);
        cudaEventCreateWithFlags(&evB, cudaEventDisableTiming);
    }

    const int smem_yx = 10 * (TY + 4) * 128 * 2 + 10 * 2 * 128 * 4;  // 61,440 B
    cudaFuncSetAttribute(k_blurYX_red,
                         cudaFuncAttributeMaxDynamicSharedMemorySize, smem_yx);

    dim3 g(VOL / 256), b(256);

    // R9's exact schedule:
    // s0: init -> pack -> warp_all -> mse_both -> (join) -> final
    // s1:                        \-> blurZ -> blurYX
    k_init<<<1, 32>>>();
    k_pack<<<VOL / 1024, 256>>>(noise, imgA, labA, imgB, labB);
    k_warp_all<<<g, b>>>(phiAB, phiBA, labA, labB);
    cudaEventRecord(evW, 0);
    cudaStreamWaitEvent(s1, evW, 0);

    k_blurZ10<<<g, b, 0, s1>>>();
    k_blurYX_red<<<1024, 256, smem_yx, s1>>>();
    cudaEventRecord(evB, s1);

    k_mse_both<<<g, b>>>(phiAB, phiBA);
    cudaStreamWaitEvent(0, evB, 0);
    k_final<<<1, 1>>>(out);
}